// round 1
// baseline (speedup 1.0000x reference)
#include <cuda_runtime.h>
#include <math.h>

#define NB 256     // batch
#define DI 512     // input dim
#define HH 512     // hidden dim
#define H4 2048    // 4*H
#define H3 1536    // 3*H
#define EPSV 1.0f
#define NITER 24

// ---------------- scratch (static device globals; no allocations) ----------------
__device__ float g_Z[NB * H4];      // pre-activations      (2 MB)
__device__ float g_C3[NB * H3];     // gate coeffs ci,cf,cg (1.5 MB)
__device__ float g_diagA[NB * HH];  // Jacobi precond
__device__ float g_S6[6 * HH];      // W_a[j]·W_b[j] sym pairs
__device__ float g_r[NB * HH];      // CG residual
__device__ float g_p[NB * HH];      // CG direction
__device__ float g_t[NB * DI];      // G^T p
__device__ float g_v[NB * H3];      // W3 t (per gate)
__device__ float g_rz[NB];          // CG scalar r.z per batch

// ---------------- S_ab[j] = W_a[j,:] . W_b[j,:] (6 symmetric pairs) ----------------
__global__ void sab_kernel(const float* __restrict__ Wih) {
    int j = blockIdx.x;       // 0..511
    int tid = threadIdx.x;    // 128 threads
    const float* w0 = Wih + (0 * HH + j) * DI;
    const float* w1 = Wih + (1 * HH + j) * DI;
    const float* w2 = Wih + (2 * HH + j) * DI;
    float s[6] = {0.f, 0.f, 0.f, 0.f, 0.f, 0.f};
    for (int d = tid; d < DI; d += 128) {
        float a = w0[d], b = w1[d], c = w2[d];
        s[0] += a * a; s[1] += a * b; s[2] += a * c;
        s[3] += b * b; s[4] += b * c; s[5] += c * c;
    }
    __shared__ float red[128];
    #pragma unroll
    for (int q = 0; q < 6; q++) {
        red[tid] = s[q];
        __syncthreads();
        for (int st = 64; st > 0; st >>= 1) {
            if (tid < st) red[tid] += red[tid + st];
            __syncthreads();
        }
        if (tid == 0) g_S6[q * HH + j] = red[0];
        __syncthreads();
    }
}

// ---------------- Z = x@Wih^T + hx@Whh^T + b_ih + b_hh  (NT GEMM, fused) ----------------
// 64x64 tile, BK=16, 256 threads, 4x4 microtile
__global__ void gemm_z_kernel(const float* __restrict__ x, const float* __restrict__ hx,
                              const float* __restrict__ Wih, const float* __restrict__ Whh,
                              const float* __restrict__ bih, const float* __restrict__ bhh) {
    __shared__ float As[16][64];
    __shared__ float Bs[16][64];
    int tid = threadIdx.x;
    int tx = tid % 16, ty = tid / 16;
    int nbase = blockIdx.y * 64;  // batch rows
    int mbase = blockIdx.x * 64;  // output cols (0..2047)
    float acc[4][4] = {};
    int lr = tid / 4;            // 0..63
    int lc = (tid % 4) * 4;      // 0,4,8,12

    #pragma unroll
    for (int src = 0; src < 2; src++) {
        const float* A = src ? hx : x;     // [256,512]
        const float* B = src ? Whh : Wih;  // [2048,512]
        for (int k0 = 0; k0 < 512; k0 += 16) {
            float4 av = *(const float4*)(A + (nbase + lr) * 512 + k0 + lc);
            As[lc + 0][lr] = av.x; As[lc + 1][lr] = av.y;
            As[lc + 2][lr] = av.z; As[lc + 3][lr] = av.w;
            float4 bv = *(const float4*)(B + (mbase + lr) * 512 + k0 + lc);
            Bs[lc + 0][lr] = bv.x; Bs[lc + 1][lr] = bv.y;
            Bs[lc + 2][lr] = bv.z; Bs[lc + 3][lr] = bv.w;
            __syncthreads();
            #pragma unroll
            for (int kk = 0; kk < 16; kk++) {
                float4 a4 = *(const float4*)&As[kk][ty * 4];
                float4 b4 = *(const float4*)&Bs[kk][tx * 4];
                acc[0][0] += a4.x * b4.x; acc[0][1] += a4.x * b4.y; acc[0][2] += a4.x * b4.z; acc[0][3] += a4.x * b4.w;
                acc[1][0] += a4.y * b4.x; acc[1][1] += a4.y * b4.y; acc[1][2] += a4.y * b4.z; acc[1][3] += a4.y * b4.w;
                acc[2][0] += a4.z * b4.x; acc[2][1] += a4.z * b4.y; acc[2][2] += a4.z * b4.z; acc[2][3] += a4.z * b4.w;
                acc[3][0] += a4.w * b4.x; acc[3][1] += a4.w * b4.y; acc[3][2] += a4.w * b4.z; acc[3][3] += a4.w * b4.w;
            }
            __syncthreads();
        }
    }
    #pragma unroll
    for (int i = 0; i < 4; i++) {
        int row = nbase + ty * 4 + i;
        #pragma unroll
        for (int jj = 0; jj < 4; jj++) {
            int col = mbase + tx * 4 + jj;
            g_Z[row * H4 + col] = acc[i][jj] + bih[col] + bhh[col];
        }
    }
}

// ---------------- gates: activations, h_new, coeffs, diag precond, CG init ----------------
__global__ void gates_kernel(const float* __restrict__ cx,
                             float* __restrict__ out_h, float* __restrict__ out_x) {
    int n = blockIdx.x, j = threadIdx.x;  // 256 blocks x 512 threads
    const float* z = g_Z + n * H4;
    float zi = z[j], zf = z[HH + j], zg = z[2 * HH + j], zo = z[3 * HH + j];
    float iv = 1.f / (1.f + expf(-zi));
    float fv = 1.f / (1.f + expf(-zf));
    float gv = tanhf(zg);
    float ov = 1.f / (1.f + expf(-zo));
    float cxv = cx[n * HH + j];
    float cn = fv * cxv + iv * gv;
    out_h[n * HH + j] = ov * tanhf(cn);

    float c0 = iv * (1.f - iv) * gv;
    float c1 = fv * (1.f - fv) * cxv;
    float c2 = (1.f - gv * gv) * iv;
    g_C3[n * H3 + j] = c0;
    g_C3[n * H3 + HH + j] = c1;
    g_C3[n * H3 + 2 * HH + j] = c2;

    float s00 = g_S6[j], s01 = g_S6[HH + j], s02 = g_S6[2 * HH + j];
    float s11 = g_S6[3 * HH + j], s12 = g_S6[4 * HH + j], s22 = g_S6[5 * HH + j];
    float dg = 1.f + EPSV * (c0 * c0 * s00 + c1 * c1 * s11 + c2 * c2 * s22 +
                             2.f * (c0 * c1 * s01 + c0 * c2 * s02 + c1 * c2 * s12));
    g_diagA[n * HH + j] = dg;

    // PCG init: x=0, r=c_new, z=r/diag, p=z, rz=r.z
    out_x[n * HH + j] = 0.f;
    float rj = cn;
    float zj = rj / dg;
    g_r[n * HH + j] = rj;
    g_p[n * HH + j] = zj;

    __shared__ float red[512];
    red[j] = rj * zj;
    __syncthreads();
    for (int s = 256; s > 0; s >>= 1) {
        if (j < s) red[j] += red[j + s];
        __syncthreads();
    }
    if (j == 0) g_rz[n] = red[0];
}

// ---------------- t = (C3 .* p) @ W3   (NN GEMM, fused A scaling) ----------------
// M=256, K=1536, N=512; 64x64 tile
__global__ void k1_kernel(const float* __restrict__ Wih) {
    __shared__ float As[16][64];
    __shared__ float Bs[16][64];
    int tid = threadIdx.x;
    int tx = tid % 16, ty = tid / 16;
    int nbase = blockIdx.y * 64;  // batch rows
    int dbase = blockIdx.x * 64;  // output cols d
    float acc[4][4] = {};
    int lr = tid / 4;            // A: row 0..63
    int lc = (tid % 4) * 4;      // A: k 0,4,8,12
    int bkr = tid / 16;          // B: k row 0..15
    int bc = (tid % 16) * 4;     // B: col*4

    for (int k0 = 0; k0 < H3; k0 += 16) {
        int row = nbase + lr;
        int l = k0 + lc;
        float4 cv = *(const float4*)(g_C3 + row * H3 + l);
        float4 pv = *(const float4*)(g_p + row * HH + (l & (HH - 1)));
        As[lc + 0][lr] = cv.x * pv.x; As[lc + 1][lr] = cv.y * pv.y;
        As[lc + 2][lr] = cv.z * pv.z; As[lc + 3][lr] = cv.w * pv.w;
        float4 bv = *(const float4*)(Wih + (k0 + bkr) * DI + dbase + bc);
        *(float4*)&Bs[bkr][bc] = bv;
        __syncthreads();
        #pragma unroll
        for (int kk = 0; kk < 16; kk++) {
            float4 a4 = *(const float4*)&As[kk][ty * 4];
            float4 b4 = *(const float4*)&Bs[kk][tx * 4];
            acc[0][0] += a4.x * b4.x; acc[0][1] += a4.x * b4.y; acc[0][2] += a4.x * b4.z; acc[0][3] += a4.x * b4.w;
            acc[1][0] += a4.y * b4.x; acc[1][1] += a4.y * b4.y; acc[1][2] += a4.y * b4.z; acc[1][3] += a4.y * b4.w;
            acc[2][0] += a4.z * b4.x; acc[2][1] += a4.z * b4.y; acc[2][2] += a4.z * b4.z; acc[2][3] += a4.z * b4.w;
            acc[3][0] += a4.w * b4.x; acc[3][1] += a4.w * b4.y; acc[3][2] += a4.w * b4.z; acc[3][3] += a4.w * b4.w;
        }
        __syncthreads();
    }
    #pragma unroll
    for (int i = 0; i < 4; i++) {
        int row = nbase + ty * 4 + i;
        #pragma unroll
        for (int jj = 0; jj < 4; jj++) {
            g_t[row * DI + dbase + tx * 4 + jj] = acc[i][jj];
        }
    }
}

// ---------------- v = t @ W3^T   (NT GEMM) ----------------
// M=256, K=512, N=1536; 64x64 tile
__global__ void k2_kernel(const float* __restrict__ Wih) {
    __shared__ float As[16][64];
    __shared__ float Bs[16][64];
    int tid = threadIdx.x;
    int tx = tid % 16, ty = tid / 16;
    int nbase = blockIdx.y * 64;  // batch rows
    int mbase = blockIdx.x * 64;  // output cols (0..1535)
    float acc[4][4] = {};
    int lr = tid / 4;
    int lc = (tid % 4) * 4;

    for (int k0 = 0; k0 < DI; k0 += 16) {
        float4 av = *(const float4*)(g_t + (nbase + lr) * DI + k0 + lc);
        As[lc + 0][lr] = av.x; As[lc + 1][lr] = av.y;
        As[lc + 2][lr] = av.z; As[lc + 3][lr] = av.w;
        float4 bv = *(const float4*)(Wih + (mbase + lr) * DI + k0 + lc);
        Bs[lc + 0][lr] = bv.x; Bs[lc + 1][lr] = bv.y;
        Bs[lc + 2][lr] = bv.z; Bs[lc + 3][lr] = bv.w;
        __syncthreads();
        #pragma unroll
        for (int kk = 0; kk < 16; kk++) {
            float4 a4 = *(const float4*)&As[kk][ty * 4];
            float4 b4 = *(const float4*)&Bs[kk][tx * 4];
            acc[0][0] += a4.x * b4.x; acc[0][1] += a4.x * b4.y; acc[0][2] += a4.x * b4.z; acc[0][3] += a4.x * b4.w;
            acc[1][0] += a4.y * b4.x; acc[1][1] += a4.y * b4.y; acc[1][2] += a4.y * b4.z; acc[1][3] += a4.y * b4.w;
            acc[2][0] += a4.z * b4.x; acc[2][1] += a4.z * b4.y; acc[2][2] += a4.z * b4.z; acc[2][3] += a4.z * b4.w;
            acc[3][0] += a4.w * b4.x; acc[3][1] += a4.w * b4.y; acc[3][2] += a4.w * b4.z; acc[3][3] += a4.w * b4.w;
        }
        __syncthreads();
    }
    #pragma unroll
    for (int i = 0; i < 4; i++) {
        int row = nbase + ty * 4 + i;
        #pragma unroll
        for (int jj = 0; jj < 4; jj++) {
            g_v[row * H3 + mbase + tx * 4 + jj] = acc[i][jj];
        }
    }
}

// ---------------- one full PCG update per batch row ----------------
__global__ void cg_update_kernel(float* __restrict__ out_x) {
    int n = blockIdx.x, j = threadIdx.x;  // 256 x 512
    __shared__ float red[512];
    __shared__ float s_alpha, s_beta;

    float pj = g_p[n * HH + j];
    float c0 = g_C3[n * H3 + j];
    float c1 = g_C3[n * H3 + HH + j];
    float c2 = g_C3[n * H3 + 2 * HH + j];
    float gp = c0 * g_v[n * H3 + j] + c1 * g_v[n * H3 + HH + j] + c2 * g_v[n * H3 + 2 * HH + j];
    float Ap = pj + EPSV * gp;

    float rzold = g_rz[n];

    // pAp reduction
    red[j] = pj * Ap;
    __syncthreads();
    for (int s = 256; s > 0; s >>= 1) {
        if (j < s) red[j] += red[j + s];
        __syncthreads();
    }
    if (j == 0) s_alpha = rzold / fmaxf(red[0], 1e-30f);
    __syncthreads();
    float alpha = s_alpha;

    float xj = out_x[n * HH + j] + alpha * pj;
    float rj = g_r[n * HH + j] - alpha * Ap;
    float zj = rj / g_diagA[n * HH + j];

    // rz_new reduction
    __syncthreads();
    red[j] = rj * zj;
    __syncthreads();
    for (int s = 256; s > 0; s >>= 1) {
        if (j < s) red[j] += red[j + s];
        __syncthreads();
    }
    if (j == 0) {
        s_beta = red[0] / fmaxf(rzold, 1e-30f);
        g_rz[n] = red[0];
    }
    __syncthreads();

    out_x[n * HH + j] = xj;
    g_r[n * HH + j] = rj;
    g_p[n * HH + j] = zj + s_beta * pj;
}

// ---------------- launch ----------------
extern "C" void kernel_launch(void* const* d_in, const int* in_sizes, int n_in,
                              void* d_out, int out_size) {
    const float* x   = (const float*)d_in[0];
    const float* hx  = (const float*)d_in[1];
    const float* cx  = (const float*)d_in[2];
    const float* Wih = (const float*)d_in[3];
    const float* Whh = (const float*)d_in[4];
    const float* bih = (const float*)d_in[5];
    const float* bhh = (const float*)d_in[6];
    float* out_h = (float*)d_out;              // [256,512] h_new
    float* out_x = out_h + NB * HH;            // [256,512] prox_c (CG solution)

    sab_kernel<<<HH, 128>>>(Wih);
    gemm_z_kernel<<<dim3(H4 / 64, NB / 64), 256>>>(x, hx, Wih, Whh, bih, bhh);
    gates_kernel<<<NB, HH>>>(cx, out_h, out_x);

    for (int it = 0; it < NITER; it++) {
        k1_kernel<<<dim3(DI / 64, NB / 64), 256>>>(Wih);
        k2_kernel<<<dim3(H3 / 64, NB / 64), 256>>>(Wih);
        cg_update_kernel<<<NB, HH>>>(out_x);
    }
}

// round 2
// speedup vs baseline: 3.7814x; 3.7814x over previous
#include <cuda_runtime.h>
#include <math.h>

#define NB 256     // batch
#define DI 512     // input dim
#define HH 512     // hidden dim
#define H4 2048    // 4*H
#define H3 1536    // 3*H
#define EPSV 1.0f
#define NITER 14

// ---------------- scratch (static device globals; no allocations) ----------------
__device__ float g_Z[NB * H4];        // pre-activations
__device__ float g_C3[NB * H3];       // gate coeffs ci,cf,cg
__device__ float g_diagA[NB * HH];    // Jacobi precond
__device__ float g_S6[6 * HH];        // W_a[j]·W_b[j] sym pairs
__device__ float g_r[NB * HH];        // CG residual
__device__ float g_p[NB * HH];        // CG direction
__device__ float g_tp[3 * NB * DI];   // split-K partials of t = (C⊙p)@W3
__device__ float g_v[NB * H3];        // W3 t
__device__ float g_rz[NB];            // CG scalar r.z per batch

// ---------------- S_ab[j] = W_a[j,:] . W_b[j,:] ----------------
__global__ void sab_kernel(const float* __restrict__ Wih) {
    int j = blockIdx.x;
    int tid = threadIdx.x;    // 128 threads
    const float* w0 = Wih + (0 * HH + j) * DI;
    const float* w1 = Wih + (1 * HH + j) * DI;
    const float* w2 = Wih + (2 * HH + j) * DI;
    float s[6] = {0.f, 0.f, 0.f, 0.f, 0.f, 0.f};
    for (int d = tid; d < DI; d += 128) {
        float a = w0[d], b = w1[d], c = w2[d];
        s[0] += a * a; s[1] += a * b; s[2] += a * c;
        s[3] += b * b; s[4] += b * c; s[5] += c * c;
    }
    __shared__ float red[128];
    #pragma unroll
    for (int q = 0; q < 6; q++) {
        red[tid] = s[q];
        __syncthreads();
        for (int st = 64; st > 0; st >>= 1) {
            if (tid < st) red[tid] += red[tid + st];
            __syncthreads();
        }
        if (tid == 0) g_S6[q * HH + j] = red[0];
        __syncthreads();
    }
}

#define FMA16()                                                                                   \
    acc[0][0] += a4.x * b4.x; acc[0][1] += a4.x * b4.y; acc[0][2] += a4.x * b4.z; acc[0][3] += a4.x * b4.w; \
    acc[1][0] += a4.y * b4.x; acc[1][1] += a4.y * b4.y; acc[1][2] += a4.y * b4.z; acc[1][3] += a4.y * b4.w; \
    acc[2][0] += a4.z * b4.x; acc[2][1] += a4.z * b4.y; acc[2][2] += a4.z * b4.z; acc[2][3] += a4.z * b4.w; \
    acc[3][0] += a4.w * b4.x; acc[3][1] += a4.w * b4.y; acc[3][2] += a4.w * b4.z; acc[3][3] += a4.w * b4.w;

// ---------------- Z = x@Wih^T + hx@Whh^T + biases (double-buffered NT GEMM) ----------------
__global__ __launch_bounds__(256) void gemm_z_kernel(const float* __restrict__ x, const float* __restrict__ hx,
                              const float* __restrict__ Wih, const float* __restrict__ Whh,
                              const float* __restrict__ bih, const float* __restrict__ bhh) {
    __shared__ float As[2][16][68];
    __shared__ float Bs[2][16][68];
    int tid = threadIdx.x;
    int tx = tid % 16, ty = tid / 16;
    int nbase = blockIdx.y * 64;
    int mbase = blockIdx.x * 64;
    int lr = tid / 4, lc = (tid % 4) * 4;
    float acc[4][4] = {};

    // step s in [0,64): src = s>>5, local k0 = (s&31)*16
    {   // prologue: step 0 (src=0)
        float4 av = *(const float4*)(x + (nbase + lr) * 512 + lc);
        float4 bv = *(const float4*)(Wih + (mbase + lr) * 512 + lc);
        As[0][lc + 0][lr] = av.x; As[0][lc + 1][lr] = av.y; As[0][lc + 2][lr] = av.z; As[0][lc + 3][lr] = av.w;
        Bs[0][lc + 0][lr] = bv.x; Bs[0][lc + 1][lr] = bv.y; Bs[0][lc + 2][lr] = bv.z; Bs[0][lc + 3][lr] = bv.w;
    }
    __syncthreads();

    for (int s = 0; s < 64; s++) {
        int cur = s & 1;
        bool nx = (s + 1 < 64);
        float4 na, nb;
        if (nx) {
            int sp = s + 1;
            const float* A = (sp >> 5) ? hx : x;
            const float* B = (sp >> 5) ? Whh : Wih;
            int k0 = (sp & 31) * 16;
            na = *(const float4*)(A + (nbase + lr) * 512 + k0 + lc);
            nb = *(const float4*)(B + (mbase + lr) * 512 + k0 + lc);
        }
        #pragma unroll
        for (int kk = 0; kk < 16; kk++) {
            float4 a4 = *(const float4*)&As[cur][kk][ty * 4];
            float4 b4 = *(const float4*)&Bs[cur][kk][tx * 4];
            FMA16();
        }
        if (nx) {
            int nb_ = cur ^ 1;
            As[nb_][lc + 0][lr] = na.x; As[nb_][lc + 1][lr] = na.y; As[nb_][lc + 2][lr] = na.z; As[nb_][lc + 3][lr] = na.w;
            Bs[nb_][lc + 0][lr] = nb.x; Bs[nb_][lc + 1][lr] = nb.y; Bs[nb_][lc + 2][lr] = nb.z; Bs[nb_][lc + 3][lr] = nb.w;
        }
        __syncthreads();
    }
    #pragma unroll
    for (int i = 0; i < 4; i++) {
        int row = nbase + ty * 4 + i;
        #pragma unroll
        for (int jj = 0; jj < 4; jj++) {
            int col = mbase + tx * 4 + jj;
            g_Z[row * H4 + col] = acc[i][jj] + bih[col] + bhh[col];
        }
    }
}

// ---------------- gates: activations, h_new, coeffs, diag, CG init ----------------
__global__ void gates_kernel(const float* __restrict__ cx,
                             float* __restrict__ out_h, float* __restrict__ out_x) {
    int n = blockIdx.x, j = threadIdx.x;  // 256 x 512
    const float* z = g_Z + n * H4;
    float zi = z[j], zf = z[HH + j], zg = z[2 * HH + j], zo = z[3 * HH + j];
    float iv = 1.f / (1.f + expf(-zi));
    float fv = 1.f / (1.f + expf(-zf));
    float gv = tanhf(zg);
    float ov = 1.f / (1.f + expf(-zo));
    float cxv = cx[n * HH + j];
    float cn = fv * cxv + iv * gv;
    out_h[n * HH + j] = ov * tanhf(cn);

    float c0 = iv * (1.f - iv) * gv;
    float c1 = fv * (1.f - fv) * cxv;
    float c2 = (1.f - gv * gv) * iv;
    g_C3[n * H3 + j] = c0;
    g_C3[n * H3 + HH + j] = c1;
    g_C3[n * H3 + 2 * HH + j] = c2;

    float s00 = g_S6[j], s01 = g_S6[HH + j], s02 = g_S6[2 * HH + j];
    float s11 = g_S6[3 * HH + j], s12 = g_S6[4 * HH + j], s22 = g_S6[5 * HH + j];
    float dg = 1.f + EPSV * (c0 * c0 * s00 + c1 * c1 * s11 + c2 * c2 * s22 +
                             2.f * (c0 * c1 * s01 + c0 * c2 * s02 + c1 * c2 * s12));
    g_diagA[n * HH + j] = dg;

    out_x[n * HH + j] = 0.f;
    float rj = cn;
    float zj = rj / dg;
    g_r[n * HH + j] = rj;
    g_p[n * HH + j] = zj;

    __shared__ float red[512];
    red[j] = rj * zj;
    __syncthreads();
    for (int s = 256; s > 0; s >>= 1) {
        if (j < s) red[j] += red[j + s];
        __syncthreads();
    }
    if (j == 0) g_rz[n] = red[0];
}

// ---------------- k1: t_a = (C_a ⊙ p) @ W_a   (split-K by gate, double-buffered) ----------------
// grid (8, 4, 3): per CTA 64x64 output, K=512
__global__ __launch_bounds__(256) void k1_kernel(const float* __restrict__ Wih) {
    __shared__ float As[2][16][68];
    __shared__ float Bs[2][16][68];
    int tid = threadIdx.x;
    int tx = tid % 16, ty = tid / 16;
    int a = blockIdx.z;
    int nbase = blockIdx.y * 64;
    int dbase = blockIdx.x * 64;
    int lr = tid / 4, lc = (tid % 4) * 4;
    int bkr = tid / 16, bc = (tid % 16) * 4;
    float acc[4][4] = {};

    const float* Crow = g_C3 + (nbase + lr) * H3 + a * HH;
    const float* Prow = g_p + (nbase + lr) * HH;
    const float* Bbase = Wih + (a * HH) * DI + dbase;

    {
        float4 rc = *(const float4*)(Crow + lc);
        float4 rp = *(const float4*)(Prow + lc);
        float4 rb = *(const float4*)(Bbase + bkr * DI + bc);
        As[0][lc + 0][lr] = rc.x * rp.x; As[0][lc + 1][lr] = rc.y * rp.y;
        As[0][lc + 2][lr] = rc.z * rp.z; As[0][lc + 3][lr] = rc.w * rp.w;
        *(float4*)&Bs[0][bkr][bc] = rb;
    }
    __syncthreads();

    for (int s = 0; s < 32; s++) {
        int cur = s & 1;
        bool nx = (s + 1 < 32);
        float4 nc, np, nb;
        if (nx) {
            int k0 = (s + 1) * 16;
            nc = *(const float4*)(Crow + k0 + lc);
            np = *(const float4*)(Prow + k0 + lc);
            nb = *(const float4*)(Bbase + (k0 + bkr) * DI + bc);
        }
        #pragma unroll
        for (int kk = 0; kk < 16; kk++) {
            float4 a4 = *(const float4*)&As[cur][kk][ty * 4];
            float4 b4 = *(const float4*)&Bs[cur][kk][tx * 4];
            FMA16();
        }
        if (nx) {
            int nbuf = cur ^ 1;
            As[nbuf][lc + 0][lr] = nc.x * np.x; As[nbuf][lc + 1][lr] = nc.y * np.y;
            As[nbuf][lc + 2][lr] = nc.z * np.z; As[nbuf][lc + 3][lr] = nc.w * np.w;
            *(float4*)&Bs[nbuf][bkr][bc] = nb;
        }
        __syncthreads();
    }
    float* outp = g_tp + a * (NB * DI);
    #pragma unroll
    for (int i = 0; i < 4; i++) {
        int row = nbase + ty * 4 + i;
        #pragma unroll
        for (int jj = 0; jj < 4; jj++) {
            outp[row * DI + dbase + tx * 4 + jj] = acc[i][jj];
        }
    }
}

// ---------------- k2: v = t @ W3^T  (t = sum of 3 partials, double-buffered NT) ----------------
// grid (24, 4): per CTA 64x64 output, K=512
__global__ __launch_bounds__(256) void k2_kernel(const float* __restrict__ Wih) {
    __shared__ float As[2][16][68];
    __shared__ float Bs[2][16][68];
    int tid = threadIdx.x;
    int tx = tid % 16, ty = tid / 16;
    int nbase = blockIdx.y * 64;
    int mbase = blockIdx.x * 64;
    int lr = tid / 4, lc = (tid % 4) * 4;
    float acc[4][4] = {};

    const float* T0 = g_tp + (nbase + lr) * DI;
    const float* T1 = T0 + NB * DI;
    const float* T2 = T0 + 2 * NB * DI;
    const float* Brow = Wih + (mbase + lr) * DI;

    {
        float4 t0 = *(const float4*)(T0 + lc);
        float4 t1 = *(const float4*)(T1 + lc);
        float4 t2 = *(const float4*)(T2 + lc);
        float4 bv = *(const float4*)(Brow + lc);
        As[0][lc + 0][lr] = t0.x + t1.x + t2.x; As[0][lc + 1][lr] = t0.y + t1.y + t2.y;
        As[0][lc + 2][lr] = t0.z + t1.z + t2.z; As[0][lc + 3][lr] = t0.w + t1.w + t2.w;
        Bs[0][lc + 0][lr] = bv.x; Bs[0][lc + 1][lr] = bv.y; Bs[0][lc + 2][lr] = bv.z; Bs[0][lc + 3][lr] = bv.w;
    }
    __syncthreads();

    for (int s = 0; s < 32; s++) {
        int cur = s & 1;
        bool nx = (s + 1 < 32);
        float4 t0, t1, t2, nb;
        if (nx) {
            int k0 = (s + 1) * 16;
            t0 = *(const float4*)(T0 + k0 + lc);
            t1 = *(const float4*)(T1 + k0 + lc);
            t2 = *(const float4*)(T2 + k0 + lc);
            nb = *(const float4*)(Brow + k0 + lc);
        }
        #pragma unroll
        for (int kk = 0; kk < 16; kk++) {
            float4 a4 = *(const float4*)&As[cur][kk][ty * 4];
            float4 b4 = *(const float4*)&Bs[cur][kk][tx * 4];
            FMA16();
        }
        if (nx) {
            int nbuf = cur ^ 1;
            As[nbuf][lc + 0][lr] = t0.x + t1.x + t2.x; As[nbuf][lc + 1][lr] = t0.y + t1.y + t2.y;
            As[nbuf][lc + 2][lr] = t0.z + t1.z + t2.z; As[nbuf][lc + 3][lr] = t0.w + t1.w + t2.w;
            Bs[nbuf][lc + 0][lr] = nb.x; Bs[nbuf][lc + 1][lr] = nb.y;
            Bs[nbuf][lc + 2][lr] = nb.z; Bs[nbuf][lc + 3][lr] = nb.w;
        }
        __syncthreads();
    }
    #pragma unroll
    for (int i = 0; i < 4; i++) {
        int row = nbase + ty * 4 + i;
        #pragma unroll
        for (int jj = 0; jj < 4; jj++) {
            g_v[row * H3 + mbase + tx * 4 + jj] = acc[i][jj];
        }
    }
}

// ---------------- one full PCG update per batch row ----------------
__global__ void cg_update_kernel(float* __restrict__ out_x) {
    int n = blockIdx.x, j = threadIdx.x;  // 256 x 512
    __shared__ float red[512];
    __shared__ float s_alpha, s_beta;

    float pj = g_p[n * HH + j];
    float c0 = g_C3[n * H3 + j];
    float c1 = g_C3[n * H3 + HH + j];
    float c2 = g_C3[n * H3 + 2 * HH + j];
    float gp = c0 * g_v[n * H3 + j] + c1 * g_v[n * H3 + HH + j] + c2 * g_v[n * H3 + 2 * HH + j];
    float Ap = pj + EPSV * gp;

    float rzold = g_rz[n];

    red[j] = pj * Ap;
    __syncthreads();
    for (int s = 256; s > 0; s >>= 1) {
        if (j < s) red[j] += red[j + s];
        __syncthreads();
    }
    if (j == 0) s_alpha = rzold / fmaxf(red[0], 1e-30f);
    __syncthreads();
    float alpha = s_alpha;

    float xj = out_x[n * HH + j] + alpha * pj;
    float rj = g_r[n * HH + j] - alpha * Ap;
    float zj = rj / g_diagA[n * HH + j];

    __syncthreads();
    red[j] = rj * zj;
    __syncthreads();
    for (int s = 256; s > 0; s >>= 1) {
        if (j < s) red[j] += red[j + s];
        __syncthreads();
    }
    if (j == 0) {
        s_beta = red[0] / fmaxf(rzold, 1e-30f);
        g_rz[n] = red[0];
    }
    __syncthreads();

    out_x[n * HH + j] = xj;
    g_r[n * HH + j] = rj;
    g_p[n * HH + j] = zj + s_beta * pj;
}

// ---------------- launch ----------------
extern "C" void kernel_launch(void* const* d_in, const int* in_sizes, int n_in,
                              void* d_out, int out_size) {
    const float* x   = (const float*)d_in[0];
    const float* hx  = (const float*)d_in[1];
    const float* cx  = (const float*)d_in[2];
    const float* Wih = (const float*)d_in[3];
    const float* Whh = (const float*)d_in[4];
    const float* bih = (const float*)d_in[5];
    const float* bhh = (const float*)d_in[6];
    float* out_h = (float*)d_out;
    float* out_x = out_h + NB * HH;

    sab_kernel<<<HH, 128>>>(Wih);
    gemm_z_kernel<<<dim3(H4 / 64, NB / 64), 256>>>(x, hx, Wih, Whh, bih, bhh);
    gates_kernel<<<NB, HH>>>(cx, out_h, out_x);

    for (int it = 0; it < NITER; it++) {
        k1_kernel<<<dim3(DI / 64, NB / 64, 3), 256>>>(Wih);
        k2_kernel<<<dim3(H3 / 64, NB / 64), 256>>>(Wih);
        cg_update_kernel<<<NB, HH>>>(out_x);
    }
}

// round 3
// speedup vs baseline: 6.4835x; 1.7145x over previous
#include <cuda_runtime.h>
#include <math.h>

#define NB 256     // batch
#define DI 512     // input dim
#define HH 512     // hidden dim
#define H4 2048    // 4*H
#define H3 1536    // 3*H
#define EPSV 1.0f
#define NITER 8

// ---------------- scratch (static device globals) ----------------
__device__ float g_Zp[2 * NB * H4];   // gemm_z partials (x-part, hx-part)
__device__ float g_C3[NB * H3];       // gate coeffs ci,cf,cg
__device__ float g_u[NB * H3];        // u = C ⊙ p (GEMM A operand)
__device__ float g_diagA[NB * HH];    // Jacobi precond
__device__ float g_S6[6 * HH];        // W_a[j]·W_b[j] sym pairs
__device__ float g_r[NB * HH];        // CG residual
__device__ float g_p[NB * HH];        // CG direction
__device__ float g_tp[6 * NB * DI];   // k1 partials: (gate,khalf)
__device__ float g_vp[2 * NB * H3];   // k2 partials: (khalf)
__device__ float g_rz[NB];            // CG scalar r.z per batch

// ---------------- S_ab[j] = W_a[j,:] . W_b[j,:] ----------------
__global__ void sab_kernel(const float* __restrict__ Wih) {
    int j = blockIdx.x;
    int tid = threadIdx.x;    // 128
    const float* w0 = Wih + (0 * HH + j) * DI;
    const float* w1 = Wih + (1 * HH + j) * DI;
    const float* w2 = Wih + (2 * HH + j) * DI;
    float s[6] = {0.f, 0.f, 0.f, 0.f, 0.f, 0.f};
    for (int d = tid; d < DI; d += 128) {
        float a = w0[d], b = w1[d], c = w2[d];
        s[0] += a * a; s[1] += a * b; s[2] += a * c;
        s[3] += b * b; s[4] += b * c; s[5] += c * c;
    }
    __shared__ float red[128];
    #pragma unroll
    for (int q = 0; q < 6; q++) {
        red[tid] = s[q];
        __syncthreads();
        for (int st = 64; st > 0; st >>= 1) {
            if (tid < st) red[tid] += red[tid + st];
            __syncthreads();
        }
        if (tid == 0) g_S6[q * HH + j] = red[0];
        __syncthreads();
    }
}

#define FMA16()                                                                                   \
    acc[0][0] += a4.x * b4.x; acc[0][1] += a4.x * b4.y; acc[0][2] += a4.x * b4.z; acc[0][3] += a4.x * b4.w; \
    acc[1][0] += a4.y * b4.x; acc[1][1] += a4.y * b4.y; acc[1][2] += a4.y * b4.z; acc[1][3] += a4.y * b4.w; \
    acc[2][0] += a4.z * b4.x; acc[2][1] += a4.z * b4.y; acc[2][2] += a4.z * b4.z; acc[2][3] += a4.z * b4.w; \
    acc[3][0] += a4.w * b4.x; acc[3][1] += a4.w * b4.y; acc[3][2] += a4.w * b4.z; acc[3][3] += a4.w * b4.w;

// ---------------- gemm_z partial: Zp[z] = (z? hx:x) @ (z? Whh:Wih)^T ----------------
// grid (32, 4, 2), 64x64 tile, K=512
__global__ __launch_bounds__(256) void gemm_z_kernel(const float* __restrict__ x, const float* __restrict__ hx,
                              const float* __restrict__ Wih, const float* __restrict__ Whh) {
    __shared__ float As[2][16][68];
    __shared__ float Bs[2][16][68];
    int tid = threadIdx.x;
    int tx = tid % 16, ty = tid / 16;
    int nbase = blockIdx.y * 64;
    int mbase = blockIdx.x * 64;
    int z = blockIdx.z;
    const float* A = z ? hx : x;
    const float* B = z ? Whh : Wih;
    int lr = tid / 4, lc = (tid % 4) * 4;
    float acc[4][4] = {};

    {
        float4 av = *(const float4*)(A + (nbase + lr) * 512 + lc);
        float4 bv = *(const float4*)(B + (mbase + lr) * 512 + lc);
        As[0][lc + 0][lr] = av.x; As[0][lc + 1][lr] = av.y; As[0][lc + 2][lr] = av.z; As[0][lc + 3][lr] = av.w;
        Bs[0][lc + 0][lr] = bv.x; Bs[0][lc + 1][lr] = bv.y; Bs[0][lc + 2][lr] = bv.z; Bs[0][lc + 3][lr] = bv.w;
    }
    __syncthreads();

    for (int s = 0; s < 32; s++) {
        int cur = s & 1;
        bool nx = (s + 1 < 32);
        float4 na, nb;
        if (nx) {
            int k0 = (s + 1) * 16;
            na = *(const float4*)(A + (nbase + lr) * 512 + k0 + lc);
            nb = *(const float4*)(B + (mbase + lr) * 512 + k0 + lc);
        }
        #pragma unroll
        for (int kk = 0; kk < 16; kk++) {
            float4 a4 = *(const float4*)&As[cur][kk][ty * 4];
            float4 b4 = *(const float4*)&Bs[cur][kk][tx * 4];
            FMA16();
        }
        if (nx) {
            int nb_ = cur ^ 1;
            As[nb_][lc + 0][lr] = na.x; As[nb_][lc + 1][lr] = na.y; As[nb_][lc + 2][lr] = na.z; As[nb_][lc + 3][lr] = na.w;
            Bs[nb_][lc + 0][lr] = nb.x; Bs[nb_][lc + 1][lr] = nb.y; Bs[nb_][lc + 2][lr] = nb.z; Bs[nb_][lc + 3][lr] = nb.w;
        }
        __syncthreads();
    }
    float* outp = g_Zp + z * (NB * H4);
    #pragma unroll
    for (int i = 0; i < 4; i++) {
        int row = nbase + ty * 4 + i;
        #pragma unroll
        for (int jj = 0; jj < 4; jj++) {
            outp[row * H4 + mbase + tx * 4 + jj] = acc[i][jj];
        }
    }
}

// ---------------- gates: activations, h_new, coeffs, diag, CG init ----------------
__global__ void gates_kernel(const float* __restrict__ cx,
                             const float* __restrict__ bih, const float* __restrict__ bhh,
                             float* __restrict__ out_h, float* __restrict__ out_x) {
    int n = blockIdx.x, j = threadIdx.x;  // 256 x 512
    const float* z0 = g_Zp + n * H4;
    const float* z1 = g_Zp + NB * H4 + n * H4;
    float zi = z0[j]          + z1[j]          + bih[j]          + bhh[j];
    float zf = z0[HH + j]     + z1[HH + j]     + bih[HH + j]     + bhh[HH + j];
    float zg = z0[2 * HH + j] + z1[2 * HH + j] + bih[2 * HH + j] + bhh[2 * HH + j];
    float zo = z0[3 * HH + j] + z1[3 * HH + j] + bih[3 * HH + j] + bhh[3 * HH + j];
    float iv = 1.f / (1.f + expf(-zi));
    float fv = 1.f / (1.f + expf(-zf));
    float gv = tanhf(zg);
    float ov = 1.f / (1.f + expf(-zo));
    float cxv = cx[n * HH + j];
    float cn = fv * cxv + iv * gv;
    out_h[n * HH + j] = ov * tanhf(cn);

    float c0 = iv * (1.f - iv) * gv;
    float c1 = fv * (1.f - fv) * cxv;
    float c2 = (1.f - gv * gv) * iv;
    g_C3[n * H3 + j] = c0;
    g_C3[n * H3 + HH + j] = c1;
    g_C3[n * H3 + 2 * HH + j] = c2;

    float s00 = g_S6[j], s01 = g_S6[HH + j], s02 = g_S6[2 * HH + j];
    float s11 = g_S6[3 * HH + j], s12 = g_S6[4 * HH + j], s22 = g_S6[5 * HH + j];
    float dg = 1.f + EPSV * (c0 * c0 * s00 + c1 * c1 * s11 + c2 * c2 * s22 +
                             2.f * (c0 * c1 * s01 + c0 * c2 * s02 + c1 * c2 * s12));
    g_diagA[n * HH + j] = dg;

    out_x[n * HH + j] = 0.f;
    float rj = cn;
    float zj = rj / dg;
    g_r[n * HH + j] = rj;
    g_p[n * HH + j] = zj;
    g_u[n * H3 + j] = c0 * zj;
    g_u[n * H3 + HH + j] = c1 * zj;
    g_u[n * H3 + 2 * HH + j] = c2 * zj;

    __shared__ float red[512];
    red[j] = rj * zj;
    __syncthreads();
    for (int s = 256; s > 0; s >>= 1) {
        if (j < s) red[j] += red[j + s];
        __syncthreads();
    }
    if (j == 0) g_rz[n] = red[0];
}

// ---------------- k1: tp[gate,kh] = u[:, gate*512+kh*256 : +256] @ W_slice ----------------
// grid (8, 4, 6), 64x64 tile, K=256
__global__ __launch_bounds__(256) void k1_kernel(const float* __restrict__ Wih) {
    __shared__ float As[2][16][68];
    __shared__ float Bs[2][16][68];
    int tid = threadIdx.x;
    int tx = tid % 16, ty = tid / 16;
    int zid = blockIdx.z;           // 0..5 : gate*2 + khalf
    int gate = zid >> 1, kh = zid & 1;
    int jbase = gate * HH + kh * 256;
    int nbase = blockIdx.y * 64;
    int dbase = blockIdx.x * 64;
    int lr = tid / 4, lc = (tid % 4) * 4;
    int bkr = tid / 16, bc = (tid % 16) * 4;
    float acc[4][4] = {};

    const float* Arow = g_u + (nbase + lr) * H3 + jbase;
    const float* Bbase = Wih + jbase * DI + dbase;

    {
        float4 ra = *(const float4*)(Arow + lc);
        float4 rb = *(const float4*)(Bbase + bkr * DI + bc);
        As[0][lc + 0][lr] = ra.x; As[0][lc + 1][lr] = ra.y; As[0][lc + 2][lr] = ra.z; As[0][lc + 3][lr] = ra.w;
        *(float4*)&Bs[0][bkr][bc] = rb;
    }
    __syncthreads();

    for (int s = 0; s < 16; s++) {
        int cur = s & 1;
        bool nx = (s + 1 < 16);
        float4 na, nb;
        if (nx) {
            int k0 = (s + 1) * 16;
            na = *(const float4*)(Arow + k0 + lc);
            nb = *(const float4*)(Bbase + (k0 + bkr) * DI + bc);
        }
        #pragma unroll
        for (int kk = 0; kk < 16; kk++) {
            float4 a4 = *(const float4*)&As[cur][kk][ty * 4];
            float4 b4 = *(const float4*)&Bs[cur][kk][tx * 4];
            FMA16();
        }
        if (nx) {
            int nbuf = cur ^ 1;
            As[nbuf][lc + 0][lr] = na.x; As[nbuf][lc + 1][lr] = na.y; As[nbuf][lc + 2][lr] = na.z; As[nbuf][lc + 3][lr] = na.w;
            *(float4*)&Bs[nbuf][bkr][bc] = nb;
        }
        __syncthreads();
    }
    float* outp = g_tp + zid * (NB * DI);
    #pragma unroll
    for (int i = 0; i < 4; i++) {
        int row = nbase + ty * 4 + i;
        #pragma unroll
        for (int jj = 0; jj < 4; jj++) {
            outp[row * DI + dbase + tx * 4 + jj] = acc[i][jj];
        }
    }
}

// ---------------- k2: vp[kh] = t[:, kh*256:+256] @ W3^T-slice  (t = Σ 6 partials) ----------------
// grid (24, 4, 2), 64x64 tile, K=256
__global__ __launch_bounds__(256) void k2_kernel(const float* __restrict__ Wih) {
    __shared__ float As[2][16][68];
    __shared__ float Bs[2][16][68];
    int tid = threadIdx.x;
    int tx = tid % 16, ty = tid / 16;
    int kh = blockIdx.z;
    int dbase0 = kh * 256;
    int nbase = blockIdx.y * 64;
    int mbase = blockIdx.x * 64;
    int lr = tid / 4, lc = (tid % 4) * 4;
    float acc[4][4] = {};

    const float* T = g_tp + (nbase + lr) * DI + dbase0;
    const float* Brow = Wih + (mbase + lr) * DI + dbase0;

    #define LOAD_TSUM(dst, off)                                               \
        {                                                                     \
            float4 t0 = *(const float4*)(T + 0 * (NB * DI) + (off));          \
            float4 t1 = *(const float4*)(T + 1 * (NB * DI) + (off));          \
            float4 t2 = *(const float4*)(T + 2 * (NB * DI) + (off));          \
            float4 t3 = *(const float4*)(T + 3 * (NB * DI) + (off));          \
            float4 t4 = *(const float4*)(T + 4 * (NB * DI) + (off));          \
            float4 t5 = *(const float4*)(T + 5 * (NB * DI) + (off));          \
            dst.x = (t0.x + t1.x) + (t2.x + t3.x) + (t4.x + t5.x);            \
            dst.y = (t0.y + t1.y) + (t2.y + t3.y) + (t4.y + t5.y);            \
            dst.z = (t0.z + t1.z) + (t2.z + t3.z) + (t4.z + t5.z);            \
            dst.w = (t0.w + t1.w) + (t2.w + t3.w) + (t4.w + t5.w);            \
        }

    {
        float4 ta; LOAD_TSUM(ta, lc);
        float4 bv = *(const float4*)(Brow + lc);
        As[0][lc + 0][lr] = ta.x; As[0][lc + 1][lr] = ta.y; As[0][lc + 2][lr] = ta.z; As[0][lc + 3][lr] = ta.w;
        Bs[0][lc + 0][lr] = bv.x; Bs[0][lc + 1][lr] = bv.y; Bs[0][lc + 2][lr] = bv.z; Bs[0][lc + 3][lr] = bv.w;
    }
    __syncthreads();

    for (int s = 0; s < 16; s++) {
        int cur = s & 1;
        bool nx = (s + 1 < 16);
        float4 ta, nb;
        if (nx) {
            int k0 = (s + 1) * 16;
            LOAD_TSUM(ta, k0 + lc);
            nb = *(const float4*)(Brow + k0 + lc);
        }
        #pragma unroll
        for (int kk = 0; kk < 16; kk++) {
            float4 a4 = *(const float4*)&As[cur][kk][ty * 4];
            float4 b4 = *(const float4*)&Bs[cur][kk][tx * 4];
            FMA16();
        }
        if (nx) {
            int nbuf = cur ^ 1;
            As[nbuf][lc + 0][lr] = ta.x; As[nbuf][lc + 1][lr] = ta.y; As[nbuf][lc + 2][lr] = ta.z; As[nbuf][lc + 3][lr] = ta.w;
            Bs[nbuf][lc + 0][lr] = nb.x; Bs[nbuf][lc + 1][lr] = nb.y; Bs[nbuf][lc + 2][lr] = nb.z; Bs[nbuf][lc + 3][lr] = nb.w;
        }
        __syncthreads();
    }
    float* outp = g_vp + kh * (NB * H3);
    #pragma unroll
    for (int i = 0; i < 4; i++) {
        int row = nbase + ty * 4 + i;
        #pragma unroll
        for (int jj = 0; jj < 4; jj++) {
            outp[row * H3 + mbase + tx * 4 + jj] = acc[i][jj];
        }
    }
}

// ---------------- PCG scalar+vector update, 256 threads (2 j each) ----------------
__global__ __launch_bounds__(256) void cg_update_kernel(float* __restrict__ out_x) {
    int n = blockIdx.x;
    int t = threadIdx.x;
    int j0 = t, j1 = t + 256;
    __shared__ float warpsum[8];
    __shared__ float s_scalar;

    const float* v0 = g_vp + n * H3;
    const float* v1 = g_vp + NB * H3 + n * H3;
    const float* C = g_C3 + n * H3;

    float p0 = g_p[n * HH + j0], p1 = g_p[n * HH + j1];
    float c00 = C[j0], c10 = C[HH + j0], c20 = C[2 * HH + j0];
    float c01 = C[j1], c11 = C[HH + j1], c21 = C[2 * HH + j1];
    float gp0 = c00 * (v0[j0] + v1[j0]) + c10 * (v0[HH + j0] + v1[HH + j0]) + c20 * (v0[2 * HH + j0] + v1[2 * HH + j0]);
    float gp1 = c01 * (v0[j1] + v1[j1]) + c11 * (v0[HH + j1] + v1[HH + j1]) + c21 * (v0[2 * HH + j1] + v1[2 * HH + j1]);
    float Ap0 = p0 + EPSV * gp0;
    float Ap1 = p1 + EPSV * gp1;

    float part = p0 * Ap0 + p1 * Ap1;
    #pragma unroll
    for (int o = 16; o > 0; o >>= 1) part += __shfl_xor_sync(0xffffffffu, part, o);
    if ((t & 31) == 0) warpsum[t >> 5] = part;
    __syncthreads();
    if (t < 8) {
        float v = warpsum[t];
        #pragma unroll
        for (int o = 4; o > 0; o >>= 1) v += __shfl_xor_sync(0xffu, v, o);
        if (t == 0) s_scalar = v;
    }
    __syncthreads();
    float rzold = g_rz[n];
    float alpha = rzold / fmaxf(s_scalar, 1e-30f);

    float x0 = out_x[n * HH + j0] + alpha * p0;
    float x1 = out_x[n * HH + j1] + alpha * p1;
    float r0 = g_r[n * HH + j0] - alpha * Ap0;
    float r1 = g_r[n * HH + j1] - alpha * Ap1;
    float z0 = r0 / g_diagA[n * HH + j0];
    float z1 = r1 / g_diagA[n * HH + j1];

    __syncthreads();
    part = r0 * z0 + r1 * z1;
    #pragma unroll
    for (int o = 16; o > 0; o >>= 1) part += __shfl_xor_sync(0xffffffffu, part, o);
    if ((t & 31) == 0) warpsum[t >> 5] = part;
    __syncthreads();
    if (t < 8) {
        float v = warpsum[t];
        #pragma unroll
        for (int o = 4; o > 0; o >>= 1) v += __shfl_xor_sync(0xffu, v, o);
        if (t == 0) { s_scalar = v; g_rz[n] = v; }
    }
    __syncthreads();
    float beta = s_scalar / fmaxf(rzold, 1e-30f);

    float pn0 = z0 + beta * p0;
    float pn1 = z1 + beta * p1;
    out_x[n * HH + j0] = x0;  out_x[n * HH + j1] = x1;
    g_r[n * HH + j0] = r0;    g_r[n * HH + j1] = r1;
    g_p[n * HH + j0] = pn0;   g_p[n * HH + j1] = pn1;
    float* U = g_u + n * H3;
    U[j0] = c00 * pn0;           U[j1] = c01 * pn1;
    U[HH + j0] = c10 * pn0;      U[HH + j1] = c11 * pn1;
    U[2 * HH + j0] = c20 * pn0;  U[2 * HH + j1] = c21 * pn1;
}

// ---------------- launch ----------------
extern "C" void kernel_launch(void* const* d_in, const int* in_sizes, int n_in,
                              void* d_out, int out_size) {
    const float* x   = (const float*)d_in[0];
    const float* hx  = (const float*)d_in[1];
    const float* cx  = (const float*)d_in[2];
    const float* Wih = (const float*)d_in[3];
    const float* Whh = (const float*)d_in[4];
    const float* bih = (const float*)d_in[5];
    const float* bhh = (const float*)d_in[6];
    float* out_h = (float*)d_out;
    float* out_x = out_h + NB * HH;

    sab_kernel<<<HH, 128>>>(Wih);
    gemm_z_kernel<<<dim3(H4 / 64, NB / 64, 2), 256>>>(x, hx, Wih, Whh);
    gates_kernel<<<NB, HH>>>(cx, bih, bhh, out_h, out_x);

    for (int it = 0; it < NITER; it++) {
        k1_kernel<<<dim3(DI / 64, NB / 64, 6), 256>>>(Wih);
        k2_kernel<<<dim3(H3 / 64, NB / 64, 2), 256>>>(Wih);
        cg_update_kernel<<<NB, 256>>>(out_x);
    }
}

// round 5
// speedup vs baseline: 9.5853x; 1.4784x over previous
#include <cuda_runtime.h>
#include <math.h>

#define NB 256     // batch
#define DI 512     // input dim
#define HH 512     // hidden dim
#define H4 2048    // 4*H
#define H3 1536    // 3*H
#define EPSV 1.0f
#define NITER 6

// ---------------- scratch (static device globals) ----------------
__device__ float g_Zp[4 * NB * H4];   // gemm_z partials (src x khalf)
__device__ float g_C3[NB * H3];       // gate coeffs ci,cf,cg
__device__ float g_u[NB * H3];        // u = C ⊙ p (GEMM A operand)
__device__ float g_diagA[NB * HH];    // Jacobi precond
__device__ float g_S6[6 * HH];        // W_a[j]·W_b[j] sym pairs
__device__ float g_r[NB * HH];        // CG residual
__device__ float g_p[NB * HH];        // CG direction
__device__ float g_tp[6 * NB * DI];   // k1 partials: (gate,khalf)
__device__ float g_vp[2 * NB * H3];   // k2 partials: (khalf)
__device__ float g_rz[NB];            // CG scalar r.z per batch

// ---------------- S_ab[j] = W_a[j,:] . W_b[j,:] ----------------
__global__ void sab_kernel(const float* __restrict__ Wih) {
    int j = blockIdx.x;
    int tid = threadIdx.x;    // 128
    const float* w0 = Wih + (0 * HH + j) * DI;
    const float* w1 = Wih + (1 * HH + j) * DI;
    const float* w2 = Wih + (2 * HH + j) * DI;
    float s[6] = {0.f, 0.f, 0.f, 0.f, 0.f, 0.f};
    for (int d = tid; d < DI; d += 128) {
        float a = w0[d], b = w1[d], c = w2[d];
        s[0] += a * a; s[1] += a * b; s[2] += a * c;
        s[3] += b * b; s[4] += b * c; s[5] += c * c;
    }
    __shared__ float red[128];
    #pragma unroll
    for (int q = 0; q < 6; q++) {
        red[tid] = s[q];
        __syncthreads();
        for (int st = 64; st > 0; st >>= 1) {
            if (tid < st) red[tid] += red[tid + st];
            __syncthreads();
        }
        if (tid == 0) g_S6[q * HH + j] = red[0];
        __syncthreads();
    }
}

#define FMA16()                                                                                   \
    acc[0][0] += a4.x * b4.x; acc[0][1] += a4.x * b4.y; acc[0][2] += a4.x * b4.z; acc[0][3] += a4.x * b4.w; \
    acc[1][0] += a4.y * b4.x; acc[1][1] += a4.y * b4.y; acc[1][2] += a4.y * b4.z; acc[1][3] += a4.y * b4.w; \
    acc[2][0] += a4.z * b4.x; acc[2][1] += a4.z * b4.y; acc[2][2] += a4.z * b4.z; acc[2][3] += a4.z * b4.w; \
    acc[3][0] += a4.w * b4.x; acc[3][1] += a4.w * b4.y; acc[3][2] += a4.w * b4.z; acc[3][3] += a4.w * b4.w;

// ======== gemm_z partial: Zp[src*2+kh] += A-slice @ B-slice^T ========
// 128 thr, tile 32(M)x64(N), K=256 ; grid (32, 8, 4)
__global__ __launch_bounds__(128) void gemm_z_kernel(const float* __restrict__ x, const float* __restrict__ hx,
                              const float* __restrict__ Wih, const float* __restrict__ Whh) {
    __shared__ float As[2][16][36];
    __shared__ float Bs[2][16][68];
    int tid = threadIdx.x;
    int tx = tid % 16, ty = tid / 16;           // compute: rows ty*4, cols tx*4
    int lr = tid / 4, lc = (tid % 4) * 4;       // A load
    int br = tid / 2, bkc = (tid % 2) * 8;      // B load (NT): 2 float4 per thread
    int zid = blockIdx.z;
    const float* A = (zid >> 1) ? hx : x;
    const float* B = (zid >> 1) ? Whh : Wih;
    int k0base = (zid & 1) * 256;
    int nbase = blockIdx.y * 32;
    int mbase = blockIdx.x * 64;
    float acc[4][4] = {};
    const float* Arow = A + (nbase + lr) * 512 + k0base;
    const float* Brow = B + (mbase + br) * 512 + k0base;

    {
        float4 ra = *(const float4*)(Arow + lc);
        As[0][lc + 0][lr] = ra.x; As[0][lc + 1][lr] = ra.y; As[0][lc + 2][lr] = ra.z; As[0][lc + 3][lr] = ra.w;
        float4 rb0 = *(const float4*)(Brow + bkc);
        float4 rb1 = *(const float4*)(Brow + bkc + 4);
        Bs[0][bkc + 0][br] = rb0.x; Bs[0][bkc + 1][br] = rb0.y; Bs[0][bkc + 2][br] = rb0.z; Bs[0][bkc + 3][br] = rb0.w;
        Bs[0][bkc + 4][br] = rb1.x; Bs[0][bkc + 5][br] = rb1.y; Bs[0][bkc + 6][br] = rb1.z; Bs[0][bkc + 7][br] = rb1.w;
    }
    __syncthreads();

    for (int s = 0; s < 16; s++) {
        int cur = s & 1;
        bool nx = (s + 1 < 16);
        float4 na, nb0, nb1;
        if (nx) {
            int k0 = (s + 1) * 16;
            na  = *(const float4*)(Arow + k0 + lc);
            nb0 = *(const float4*)(Brow + k0 + bkc);
            nb1 = *(const float4*)(Brow + k0 + bkc + 4);
        }
        #pragma unroll
        for (int kk = 0; kk < 16; kk++) {
            float4 a4 = *(const float4*)&As[cur][kk][ty * 4];
            float4 b4 = *(const float4*)&Bs[cur][kk][tx * 4];
            FMA16();
        }
        if (nx) {
            int nb_ = cur ^ 1;
            As[nb_][lc + 0][lr] = na.x; As[nb_][lc + 1][lr] = na.y; As[nb_][lc + 2][lr] = na.z; As[nb_][lc + 3][lr] = na.w;
            Bs[nb_][bkc + 0][br] = nb0.x; Bs[nb_][bkc + 1][br] = nb0.y; Bs[nb_][bkc + 2][br] = nb0.z; Bs[nb_][bkc + 3][br] = nb0.w;
            Bs[nb_][bkc + 4][br] = nb1.x; Bs[nb_][bkc + 5][br] = nb1.y; Bs[nb_][bkc + 6][br] = nb1.z; Bs[nb_][bkc + 7][br] = nb1.w;
        }
        __syncthreads();
    }
    float* outp = g_Zp + zid * (NB * H4);
    #pragma unroll
    for (int i = 0; i < 4; i++) {
        int row = nbase + ty * 4 + i;
        #pragma unroll
        for (int jj = 0; jj < 4; jj++) {
            outp[row * H4 + mbase + tx * 4 + jj] = acc[i][jj];
        }
    }
}

// ---------------- gates: activations, h_new, coeffs, diag, CG init ----------------
__global__ void gates_kernel(const float* __restrict__ cx,
                             const float* __restrict__ bih, const float* __restrict__ bhh,
                             float* __restrict__ out_h, float* __restrict__ out_x) {
    int n = blockIdx.x, j = threadIdx.x;  // 256 x 512
    const float* z0 = g_Zp + 0 * NB * H4 + n * H4;
    const float* z1 = g_Zp + 1 * NB * H4 + n * H4;
    const float* z2 = g_Zp + 2 * NB * H4 + n * H4;
    const float* z3 = g_Zp + 3 * NB * H4 + n * H4;
    #define ZSUM(o) (z0[o] + z1[o] + z2[o] + z3[o] + bih[o] + bhh[o])
    float zi = ZSUM(j);
    float zf = ZSUM(HH + j);
    float zg = ZSUM(2 * HH + j);
    float zo = ZSUM(3 * HH + j);
    float iv = 1.f / (1.f + expf(-zi));
    float fv = 1.f / (1.f + expf(-zf));
    float gv = tanhf(zg);
    float ov = 1.f / (1.f + expf(-zo));
    float cxv = cx[n * HH + j];
    float cn = fv * cxv + iv * gv;
    out_h[n * HH + j] = ov * tanhf(cn);

    float c0 = iv * (1.f - iv) * gv;
    float c1 = fv * (1.f - fv) * cxv;
    float c2 = (1.f - gv * gv) * iv;
    g_C3[n * H3 + j] = c0;
    g_C3[n * H3 + HH + j] = c1;
    g_C3[n * H3 + 2 * HH + j] = c2;

    float s00 = g_S6[j], s01 = g_S6[HH + j], s02 = g_S6[2 * HH + j];
    float s11 = g_S6[3 * HH + j], s12 = g_S6[4 * HH + j], s22 = g_S6[5 * HH + j];
    float dg = 1.f + EPSV * (c0 * c0 * s00 + c1 * c1 * s11 + c2 * c2 * s22 +
                             2.f * (c0 * c1 * s01 + c0 * c2 * s02 + c1 * c2 * s12));
    g_diagA[n * HH + j] = dg;

    out_x[n * HH + j] = 0.f;
    float rj = cn;
    float zj = rj / dg;
    g_r[n * HH + j] = rj;
    g_p[n * HH + j] = zj;
    g_u[n * H3 + j] = c0 * zj;
    g_u[n * H3 + HH + j] = c1 * zj;
    g_u[n * H3 + 2 * HH + j] = c2 * zj;

    __shared__ float red[512];
    red[j] = rj * zj;
    __syncthreads();
    for (int s = 256; s > 0; s >>= 1) {
        if (j < s) red[j] += red[j + s];
        __syncthreads();
    }
    if (j == 0) g_rz[n] = red[0];
}

// ======== k1: tp[gate,kh] = u-slice @ W-slice  (NN) ========
// 128 thr, tile 32x64, K=256 ; grid (8, 8, 6)
__global__ __launch_bounds__(128) void k1_kernel(const float* __restrict__ Wih) {
    __shared__ float As[2][16][36];
    __shared__ float Bs[2][16][68];
    int tid = threadIdx.x;
    int tx = tid % 16, ty = tid / 16;
    int lr = tid / 4, lc = (tid % 4) * 4;
    int bkr = tid / 16, bc = (tid % 16) * 4;    // B (NN): k-rows bkr, bkr+8
    int zid = blockIdx.z;
    int gate = zid >> 1, kh = zid & 1;
    int jbase = gate * HH + kh * 256;
    int nbase = blockIdx.y * 32;
    int dbase = blockIdx.x * 64;
    float acc[4][4] = {};

    const float* Arow = g_u + (nbase + lr) * H3 + jbase;
    const float* Bb = Wih + jbase * DI + dbase;

    {
        float4 ra = *(const float4*)(Arow + lc);
        As[0][lc + 0][lr] = ra.x; As[0][lc + 1][lr] = ra.y; As[0][lc + 2][lr] = ra.z; As[0][lc + 3][lr] = ra.w;
        *(float4*)&Bs[0][bkr][bc]     = *(const float4*)(Bb + bkr * DI + bc);
        *(float4*)&Bs[0][bkr + 8][bc] = *(const float4*)(Bb + (bkr + 8) * DI + bc);
    }
    __syncthreads();

    for (int s = 0; s < 16; s++) {
        int cur = s & 1;
        bool nx = (s + 1 < 16);
        float4 na, nb0, nb1;
        if (nx) {
            int k0 = (s + 1) * 16;
            na  = *(const float4*)(Arow + k0 + lc);
            nb0 = *(const float4*)(Bb + (k0 + bkr) * DI + bc);
            nb1 = *(const float4*)(Bb + (k0 + bkr + 8) * DI + bc);
        }
        #pragma unroll
        for (int kk = 0; kk < 16; kk++) {
            float4 a4 = *(const float4*)&As[cur][kk][ty * 4];
            float4 b4 = *(const float4*)&Bs[cur][kk][tx * 4];
            FMA16();
        }
        if (nx) {
            int nbuf = cur ^ 1;
            As[nbuf][lc + 0][lr] = na.x; As[nbuf][lc + 1][lr] = na.y; As[nbuf][lc + 2][lr] = na.z; As[nbuf][lc + 3][lr] = na.w;
            *(float4*)&Bs[nbuf][bkr][bc] = nb0;
            *(float4*)&Bs[nbuf][bkr + 8][bc] = nb1;
        }
        __syncthreads();
    }
    float* outp = g_tp + zid * (NB * DI);
    #pragma unroll
    for (int i = 0; i < 4; i++) {
        int row = nbase + ty * 4 + i;
        #pragma unroll
        for (int jj = 0; jj < 4; jj++) {
            outp[row * DI + dbase + tx * 4 + jj] = acc[i][jj];
        }
    }
}

// ======== k2: vp[kh] = (Σ tp) @ W3^T-slice (NT) ========
// 128 thr, tile 32x64, K=256 ; grid (24, 8, 2)
__global__ __launch_bounds__(128) void k2_kernel(const float* __restrict__ Wih) {
    __shared__ float As[2][16][36];
    __shared__ float Bs[2][16][68];
    int tid = threadIdx.x;
    int tx = tid % 16, ty = tid / 16;
    int lr = tid / 4, lc = (tid % 4) * 4;
    int br = tid / 2, bkc = (tid % 2) * 8;
    int kh = blockIdx.z;
    int dbase0 = kh * 256;
    int nbase = blockIdx.y * 32;
    int mbase = blockIdx.x * 64;
    float acc[4][4] = {};

    const float* T = g_tp + (nbase + lr) * DI + dbase0;
    const float* Brow = Wih + (mbase + br) * DI + dbase0;

    #define LOAD_TSUM(dst, off)                                               \
        {                                                                     \
            float4 t0 = *(const float4*)(T + 0 * (NB * DI) + (off));          \
            float4 t1 = *(const float4*)(T + 1 * (NB * DI) + (off));          \
            float4 t2 = *(const float4*)(T + 2 * (NB * DI) + (off));          \
            float4 t3 = *(const float4*)(T + 3 * (NB * DI) + (off));          \
            float4 t4 = *(const float4*)(T + 4 * (NB * DI) + (off));          \
            float4 t5 = *(const float4*)(T + 5 * (NB * DI) + (off));          \
            dst.x = (t0.x + t1.x) + (t2.x + t3.x) + (t4.x + t5.x);            \
            dst.y = (t0.y + t1.y) + (t2.y + t3.y) + (t4.y + t5.y);            \
            dst.z = (t0.z + t1.z) + (t2.z + t3.z) + (t4.z + t5.z);            \
            dst.w = (t0.w + t1.w) + (t2.w + t3.w) + (t4.w + t5.w);            \
        }

    {
        float4 ta; LOAD_TSUM(ta, lc);
        As[0][lc + 0][lr] = ta.x; As[0][lc + 1][lr] = ta.y; As[0][lc + 2][lr] = ta.z; As[0][lc + 3][lr] = ta.w;
        float4 rb0 = *(const float4*)(Brow + bkc);
        float4 rb1 = *(const float4*)(Brow + bkc + 4);
        Bs[0][bkc + 0][br] = rb0.x; Bs[0][bkc + 1][br] = rb0.y; Bs[0][bkc + 2][br] = rb0.z; Bs[0][bkc + 3][br] = rb0.w;
        Bs[0][bkc + 4][br] = rb1.x; Bs[0][bkc + 5][br] = rb1.y; Bs[0][bkc + 6][br] = rb1.z; Bs[0][bkc + 7][br] = rb1.w;
    }
    __syncthreads();

    for (int s = 0; s < 16; s++) {
        int cur = s & 1;
        bool nx = (s + 1 < 16);
        float4 ta, nb0, nb1;
        if (nx) {
            int k0 = (s + 1) * 16;
            LOAD_TSUM(ta, k0 + lc);
            nb0 = *(const float4*)(Brow + k0 + bkc);
            nb1 = *(const float4*)(Brow + k0 + bkc + 4);
        }
        #pragma unroll
        for (int kk = 0; kk < 16; kk++) {
            float4 a4 = *(const float4*)&As[cur][kk][ty * 4];
            float4 b4 = *(const float4*)&Bs[cur][kk][tx * 4];
            FMA16();
        }
        if (nx) {
            int nbuf = cur ^ 1;
            As[nbuf][lc + 0][lr] = ta.x; As[nbuf][lc + 1][lr] = ta.y; As[nbuf][lc + 2][lr] = ta.z; As[nbuf][lc + 3][lr] = ta.w;
            Bs[nbuf][bkc + 0][br] = nb0.x; Bs[nbuf][bkc + 1][br] = nb0.y; Bs[nbuf][bkc + 2][br] = nb0.z; Bs[nbuf][bkc + 3][br] = nb0.w;
            Bs[nbuf][bkc + 4][br] = nb1.x; Bs[nbuf][bkc + 5][br] = nb1.y; Bs[nbuf][bkc + 6][br] = nb1.z; Bs[nbuf][bkc + 7][br] = nb1.w;
        }
        __syncthreads();
    }
    float* outp = g_vp + kh * (NB * H3);
    #pragma unroll
    for (int i = 0; i < 4; i++) {
        int row = nbase + ty * 4 + i;
        #pragma unroll
        for (int jj = 0; jj < 4; jj++) {
            outp[row * H3 + mbase + tx * 4 + jj] = acc[i][jj];
        }
    }
}

// ---------------- PCG scalar+vector update, 256 threads (2 j each) ----------------
__global__ __launch_bounds__(256) void cg_update_kernel(float* __restrict__ out_x) {
    int n = blockIdx.x;
    int t = threadIdx.x;
    int j0 = t, j1 = t + 256;
    __shared__ float warpsum[8];
    __shared__ float s_scalar;

    const float* v0 = g_vp + n * H3;
    const float* v1 = g_vp + NB * H3 + n * H3;
    const float* C = g_C3 + n * H3;

    float p0 = g_p[n * HH + j0], p1 = g_p[n * HH + j1];
    float c00 = C[j0], c10 = C[HH + j0], c20 = C[2 * HH + j0];
    float c01 = C[j1], c11 = C[HH + j1], c21 = C[2 * HH + j1];
    float gp0 = c00 * (v0[j0] + v1[j0]) + c10 * (v0[HH + j0] + v1[HH + j0]) + c20 * (v0[2 * HH + j0] + v1[2 * HH + j0]);
    float gp1 = c01 * (v0[j1] + v1[j1]) + c11 * (v0[HH + j1] + v1[HH + j1]) + c21 * (v0[2 * HH + j1] + v1[2 * HH + j1]);
    float Ap0 = p0 + EPSV * gp0;
    float Ap1 = p1 + EPSV * gp1;

    float part = p0 * Ap0 + p1 * Ap1;
    #pragma unroll
    for (int o = 16; o > 0; o >>= 1) part += __shfl_xor_sync(0xffffffffu, part, o);
    if ((t & 31) == 0) warpsum[t >> 5] = part;
    __syncthreads();
    if (t < 8) {
        float v = warpsum[t];
        #pragma unroll
        for (int o = 4; o > 0; o >>= 1) v += __shfl_xor_sync(0xffu, v, o);
        if (t == 0) s_scalar = v;
    }
    __syncthreads();
    float rzold = g_rz[n];
    float alpha = rzold / fmaxf(s_scalar, 1e-30f);

    float x0 = out_x[n * HH + j0] + alpha * p0;
    float x1 = out_x[n * HH + j1] + alpha * p1;
    float r0 = g_r[n * HH + j0] - alpha * Ap0;
    float r1 = g_r[n * HH + j1] - alpha * Ap1;
    float z0 = r0 / g_diagA[n * HH + j0];
    float z1 = r1 / g_diagA[n * HH + j1];

    __syncthreads();
    part = r0 * z0 + r1 * z1;
    #pragma unroll
    for (int o = 16; o > 0; o >>= 1) part += __shfl_xor_sync(0xffffffffu, part, o);
    if ((t & 31) == 0) warpsum[t >> 5] = part;
    __syncthreads();
    if (t < 8) {
        float v = warpsum[t];
        #pragma unroll
        for (int o = 4; o > 0; o >>= 1) v += __shfl_xor_sync(0xffu, v, o);
        if (t == 0) { s_scalar = v; g_rz[n] = v; }
    }
    __syncthreads();
    float beta = s_scalar / fmaxf(rzold, 1e-30f);

    float pn0 = z0 + beta * p0;
    float pn1 = z1 + beta * p1;
    out_x[n * HH + j0] = x0;  out_x[n * HH + j1] = x1;
    g_r[n * HH + j0] = r0;    g_r[n * HH + j1] = r1;
    g_p[n * HH + j0] = pn0;   g_p[n * HH + j1] = pn1;
    float* U = g_u + n * H3;
    U[j0] = c00 * pn0;           U[j1] = c01 * pn1;
    U[HH + j0] = c10 * pn0;      U[HH + j1] = c11 * pn1;
    U[2 * HH + j0] = c20 * pn0;  U[2 * HH + j1] = c21 * pn1;
}

// ---------------- launch ----------------
extern "C" void kernel_launch(void* const* d_in, const int* in_sizes, int n_in,
                              void* d_out, int out_size) {
    const float* x   = (const float*)d_in[0];
    const float* hx  = (const float*)d_in[1];
    const float* cx  = (const float*)d_in[2];
    const float* Wih = (const float*)d_in[3];
    const float* Whh = (const float*)d_in[4];
    const float* bih = (const float*)d_in[5];
    const float* bhh = (const float*)d_in[6];
    float* out_h = (float*)d_out;
    float* out_x = out_h + NB * HH;

    sab_kernel<<<HH, 128>>>(Wih);
    gemm_z_kernel<<<dim3(H4 / 64, NB / 32, 4), 128>>>(x, hx, Wih, Whh);
    gates_kernel<<<NB, HH>>>(cx, bih, bhh, out_h, out_x);

    for (int it = 0; it < NITER; it++) {
        k1_kernel<<<dim3(DI / 64, NB / 32, 6), 128>>>(Wih);
        k2_kernel<<<dim3(H3 / 64, NB / 32, 2), 128>>>(Wih);
        cg_update_kernel<<<NB, 256>>>(out_x);
    }
}